// round 16
// baseline (speedup 1.0000x reference)
#include <cuda_runtime.h>
#include <cuda_fp16.h>
#include <cstdint>

// ===========================================================================
// TrainableMPOLayer: y = X @ W^T + bias, W = dense collapse of 3-core MPO.
//   1) build_w_fused: 2048 blocks, each (ii, 32 jj): T01 slice in smem from
//      core0/core1, then W tile = T01 x (core2 * 2^14) -> fp16. 3 CTAs/SM.
//   2) Xhf = fp16(x)
//   3) Y = (Xhf @ Whf^T) * 2^-14 + bias   single-term fp16 HMMA GEMM
//      (R11-proven 3-stage schedule: wait -> barrier -> prefetch)
// ===========================================================================

#define KDIM 4096
#define MDIM 1024
#define NDIM 4096
#define WSCALE 16384.0f
#define WINV   (1.0f / 16384.0f)

__device__ __half  g_Whf[(size_t)4096 * 4096]; // 32 MB (W * 2^14)
__device__ __half  g_Xhf[(size_t)1024 * 4096]; // 8 MB

// ---------------------------------------------------------------------------
// helpers
// ---------------------------------------------------------------------------
__device__ __forceinline__ uint32_t smem_u32(const void* p) {
    uint32_t a;
    asm("{ .reg .u64 t; cvta.to.shared.u64 t, %1; cvt.u32.u64 %0, t; }"
        : "=r"(a) : "l"(p));
    return a;
}

__device__ __forceinline__ void cpasync16(uint32_t dst, const void* src) {
    asm volatile("cp.async.cg.shared.global [%0], [%1], 16;"
                 :: "r"(dst), "l"(src) : "memory");
}

__device__ __forceinline__ void ldsm4(uint32_t& r0, uint32_t& r1,
                                      uint32_t& r2, uint32_t& r3, uint32_t a) {
    asm volatile("ldmatrix.sync.aligned.m8n8.x4.shared.b16 {%0,%1,%2,%3}, [%4];"
                 : "=r"(r0), "=r"(r1), "=r"(r2), "=r"(r3) : "r"(a));
}

__device__ __forceinline__ void mma16816(float* d, const uint32_t* a,
                                         uint32_t b0, uint32_t b1) {
    asm volatile(
        "mma.sync.aligned.m16n8k16.row.col.f32.f16.f16.f32 "
        "{%0,%1,%2,%3}, {%4,%5,%6,%7}, {%8,%9}, {%0,%1,%2,%3};"
        : "+f"(d[0]), "+f"(d[1]), "+f"(d[2]), "+f"(d[3])
        : "r"(a[0]), "r"(a[1]), "r"(a[2]), "r"(a[3]), "r"(b0), "r"(b1));
}

// ---------------------------------------------------------------------------
// Kernel 1 (FUSED W BUILD): block = (ii, jjb of 32). Computes
//   t01t[r2][jjloc] = sum_r1 c0[i1,j1,r1] * c1[r1,i2,j2,r2]   (in smem)
//   W[ii*16+i3, (jjb+jjloc)*16 + j3] = sum_r2 t01t * (c2 * 2^14) -> fp16
// 2048 blocks x 256 thr; acc[2][16] (32 regs) -> 3 CTAs/SM.
// ---------------------------------------------------------------------------
#define T01T_PITCH 36
#define NWBLK 2048

__global__ __launch_bounds__(256)
void build_w_fused_kernel(const float* __restrict__ c0,
                          const float* __restrict__ c1,
                          const float* __restrict__ c2) {
    __shared__ __align__(16) float c2s[32 * 256];
    __shared__ __align__(16) float t01t[32 * T01T_PITCH];

    const int tid = threadIdx.x;
    const int ii  = blockIdx.x >> 3;          // 0..255
    const int jjb = (blockIdx.x & 7) * 32;    // 0,32,...,224
    const int i1  = ii >> 4, i2 = ii & 15;

    // stage c2 pre-scaled by 2^14 (exact power of two)
#pragma unroll
    for (int c = tid; c < 2048; c += 256) {
        float4 v = *(const float4*)&c2[c * 4];
        v.x *= WSCALE; v.y *= WSCALE; v.z *= WSCALE; v.w *= WSCALE;
        *(float4*)&c2s[c * 4] = v;
    }

    // phase 1 (threads 0-127): t01 slice. r2q fastest -> coalesced c1 loads.
    if (tid < 128) {
        const int r2q = tid & 7;
        const int j2  = tid >> 3;              // 0..15
        const float4* b = (const float4*)(c1 + i2 * 512 + j2 * 32 + r2q * 4);
        const float*  a = c0 + (i1 * 16 + (jjb >> 4)) * 32;   // 2 rows of 32

        float4 s[2];
        s[0] = make_float4(0.f, 0.f, 0.f, 0.f);
        s[1] = make_float4(0.f, 0.f, 0.f, 0.f);
#pragma unroll
        for (int r1 = 0; r1 < 32; ++r1) {
            float4 bv = b[(size_t)r1 * 2048];
#pragma unroll
            for (int v = 0; v < 2; ++v) {
                float av = a[v * 32 + r1];
                s[v].x += av * bv.x; s[v].y += av * bv.y;
                s[v].z += av * bv.z; s[v].w += av * bv.w;
            }
        }
#pragma unroll
        for (int v = 0; v < 2; ++v) {
            int jjloc = v * 16 + j2;           // 0..31
            t01t[(r2q * 4 + 0) * T01T_PITCH + jjloc] = s[v].x;
            t01t[(r2q * 4 + 1) * T01T_PITCH + jjloc] = s[v].y;
            t01t[(r2q * 4 + 2) * T01T_PITCH + jjloc] = s[v].z;
            t01t[(r2q * 4 + 3) * T01T_PITCH + jjloc] = s[v].w;
        }
    }
    __syncthreads();

    // phase 2: W tile. i3 = tid>>4 (c2 broadcast), jjg = tid&15 (2 jj each).
    const int i3  = tid >> 4;
    const int jjg = tid & 15;

    float acc[2][16];
#pragma unroll
    for (int a = 0; a < 2; ++a)
#pragma unroll
        for (int b = 0; b < 16; ++b) acc[a][b] = 0.f;

#pragma unroll
    for (int r2 = 0; r2 < 32; ++r2) {
        float2 tv = *(const float2*)&t01t[r2 * T01T_PITCH + jjg * 2];
        const float* crow = &c2s[r2 * 256 + i3 * 16];
        float4 cv0 = *(const float4*)&crow[0];
        float4 cv1 = *(const float4*)&crow[4];
        float4 cv2 = *(const float4*)&crow[8];
        float4 cv3 = *(const float4*)&crow[12];
        float cva[16] = {cv0.x, cv0.y, cv0.z, cv0.w, cv1.x, cv1.y, cv1.z, cv1.w,
                         cv2.x, cv2.y, cv2.z, cv2.w, cv3.x, cv3.y, cv3.z, cv3.w};
        float tva[2] = {tv.x, tv.y};
#pragma unroll
        for (int a = 0; a < 2; ++a)
#pragma unroll
            for (int b = 0; b < 16; ++b)
                acc[a][b] += tva[a] * cva[b];
    }

    const size_t rowoff = (size_t)(ii * 16 + i3) * 4096;
#pragma unroll
    for (int a = 0; a < 2; ++a) {
        const size_t o = rowoff + (size_t)(jjb + jjg * 2 + a) * 16;
        __half2 buf[8];
#pragma unroll
        for (int p = 0; p < 8; ++p)
            buf[p] = __half2(__float2half(acc[a][2 * p]),
                             __float2half(acc[a][2 * p + 1]));
        *(uint4*)(g_Whf + o)     = *(uint4*)&buf[0];
        *(uint4*)(g_Whf + o + 8) = *(uint4*)&buf[4];
    }
}

// ---------------------------------------------------------------------------
// Kernel 2: X -> fp16
// ---------------------------------------------------------------------------
__global__ void split_x_kernel(const float* __restrict__ x) {
    int idx = blockIdx.x * blockDim.x + threadIdx.x;   // over 1M float4s
    float4 v = ((const float4*)x)[idx];
    __half2* Hp = (__half2*)g_Xhf;
    Hp[idx * 2 + 0] = __half2(__float2half(v.x), __float2half(v.y));
    Hp[idx * 2 + 1] = __half2(__float2half(v.z), __float2half(v.w));
}

// ---------------------------------------------------------------------------
// Kernel 3: fp16 HMMA GEMM. C = (Xhf @ Whf^T) * 2^-14 + bias
// CTA 128x128, BK=64, SW128 swizzle, 3-stage cp.async, 256 threads.
// 8 warps = 4(M) x 2(N); warp tile 32x64. 2 CTAs/SM. (R11 schedule)
// ---------------------------------------------------------------------------
#define GBM 128
#define GBN 128
#define GBK 64
#define NKT (KDIM / GBK)            // 64
#define ST_A 0
#define ST_B 16384
#define STAGE_BYTES 32768
#define NSTAGE 3
#define SMEM_TOTAL (NSTAGE * STAGE_BYTES)   // 96 KB -> 2 CTAs/SM
#define NTHREADS 256

__device__ __forceinline__ void load_stage(uint32_t st, int bm, int bn,
                                           int kt, int tid) {
    const size_t krow = (size_t)kt * 128;     // byte offset within K row
#pragma unroll
    for (int c = tid; c < 2048; c += NTHREADS) {   // A:1024 + B:1024 chunks
        int arr = c >> 10;                  // 0 = A, 1 = B
        int r   = c & 1023;
        int row = r >> 3, ch = r & 7;
        uint32_t so = (uint32_t)(row * 128 + ch * 16);
        so ^= (so >> 3) & 0x70;
        if (arr == 0) {
            const size_t ga = (size_t)(bm + row) * 8192 + krow + ch * 16;
            cpasync16(st + ST_A + so, (const char*)g_Xhf + ga);
        } else {
            const size_t gb = (size_t)(bn + row) * 8192 + krow + ch * 16;
            cpasync16(st + ST_B + so, (const char*)g_Whf + gb);
        }
    }
}

__global__ __launch_bounds__(NTHREADS)
void gemm_mma_kernel(const float* __restrict__ bias, float* __restrict__ C) {
    extern __shared__ __align__(1024) char smem[];
    const uint32_t sbase = smem_u32(smem);
    const int tid  = threadIdx.x;
    const int lane = tid & 31;
    const int wid  = tid >> 5;
    const int wm = wid & 3;          // 4 M-warps (32 rows each)
    const int wn = wid >> 2;         // 2 N-warps (64 cols each)
    const int bm = blockIdx.y * GBM;
    const int bn = blockIdx.x * GBN;

    const int lrow = lane & 15;
    const uint32_t lchunk = (uint32_t)((lane >> 4) * 16);

    uint32_t a_base[2], a_mask[2];
#pragma unroll
    for (int mt = 0; mt < 2; ++mt) {
        int r = wm * 32 + mt * 16 + lrow;
        a_base[mt] = (uint32_t)(r * 128);
        a_mask[mt] = (uint32_t)((r & 7) << 4);
    }
    uint32_t b_base[4], b_mask[4];
#pragma unroll
    for (int c = 0; c < 4; ++c) {
        int r = wn * 64 + c * 16 + lrow;
        b_base[c] = (uint32_t)(r * 128);
        b_mask[c] = (uint32_t)((r & 7) << 4);
    }

    float acc[2][8][4];
#pragma unroll
    for (int mt = 0; mt < 2; ++mt)
#pragma unroll
        for (int nt = 0; nt < 8; ++nt)
#pragma unroll
            for (int e = 0; e < 4; ++e) acc[mt][nt][e] = 0.f;

    load_stage(sbase + 0 * STAGE_BYTES, bm, bn, 0, tid);
    asm volatile("cp.async.commit_group;" ::: "memory");
    load_stage(sbase + 1 * STAGE_BYTES, bm, bn, 1, tid);
    asm volatile("cp.async.commit_group;" ::: "memory");

    int slot = 0;
    for (int kt = 0; kt < NKT; ++kt) {
        if (kt + 1 < NKT)
            asm volatile("cp.async.wait_group 1;" ::: "memory");
        else
            asm volatile("cp.async.wait_group 0;" ::: "memory");
        __syncthreads();   // all warps done with slot (kt-1)%3; tile kt landed

        if (kt + 2 < NKT) {
            int ns = slot + 2; if (ns >= NSTAGE) ns -= NSTAGE;
            load_stage(sbase + ns * STAGE_BYTES, bm, bn, kt + 2, tid);
            asm volatile("cp.async.commit_group;" ::: "memory");
        }

        const uint32_t st = sbase + slot * STAGE_BYTES;
#pragma unroll
        for (int ks = 0; ks < 4; ++ks) {
            const uint32_t kb = (uint32_t)(ks * 32);
            uint32_t ah[2][4];
#pragma unroll
            for (int mt = 0; mt < 2; ++mt) {
                uint32_t col = (lchunk + kb) ^ a_mask[mt];
                ldsm4(ah[mt][0], ah[mt][1], ah[mt][2], ah[mt][3],
                      st + ST_A + a_base[mt] + col);
            }
#pragma unroll
            for (int c = 0; c < 4; ++c) {
                uint32_t col = (lchunk + kb) ^ b_mask[c];
                uint32_t bh[4];
                ldsm4(bh[0], bh[1], bh[2], bh[3], st + ST_B + b_base[c] + col);
#pragma unroll
                for (int mt = 0; mt < 2; ++mt)
#pragma unroll
                    for (int o = 0; o < 2; ++o)
                        mma16816(acc[mt][c * 2 + o], ah[mt], bh[o], bh[o + 2]);
            }
        }
        ++slot; if (slot >= NSTAGE) slot = 0;
    }

    // epilogue: undo 2^14 W scaling (exact), add bias
    const int gq = lane >> 2, rq = lane & 3;
#pragma unroll
    for (int mt = 0; mt < 2; ++mt) {
        const int r0 = bm + wm * 32 + mt * 16 + gq;
#pragma unroll
        for (int nt = 0; nt < 8; ++nt) {
            const int col = bn + wn * 64 + nt * 8 + rq * 2;
            float2 bv = *(const float2*)&bias[col];
            float2 o0 = make_float2(acc[mt][nt][0] * WINV + bv.x,
                                    acc[mt][nt][1] * WINV + bv.y);
            float2 o1 = make_float2(acc[mt][nt][2] * WINV + bv.x,
                                    acc[mt][nt][3] * WINV + bv.y);
            *(float2*)&C[(size_t)r0 * NDIM + col]       = o0;
            *(float2*)&C[(size_t)(r0 + 8) * NDIM + col] = o1;
        }
    }
}

// ---------------------------------------------------------------------------
extern "C" void kernel_launch(void* const* d_in, const int* in_sizes, int n_in,
                              void* d_out, int out_size) {
    const float* x     = (const float*)d_in[0];
    const float* core0 = (const float*)d_in[1];
    const float* core1 = (const float*)d_in[2];
    const float* core2 = (const float*)d_in[3];
    const float* bias  = (const float*)d_in[4];
    float* out = (float*)d_out;

    build_w_fused_kernel<<<NWBLK, 256>>>(core0, core1, core2);
    split_x_kernel<<<(MDIM * KDIM / 4) / 256, 256>>>(x);

    cudaFuncSetAttribute(gemm_mma_kernel,
                         cudaFuncAttributeMaxDynamicSharedMemorySize, SMEM_TOTAL);
    gemm_mma_kernel<<<dim3(NDIM / GBN, MDIM / GBM), NTHREADS, SMEM_TOTAL>>>(bias, out);
}

// round 17
// speedup vs baseline: 1.0314x; 1.0314x over previous
#include <cuda_runtime.h>
#include <cuda_fp16.h>
#include <cstdint>

// ===========================================================================
// TrainableMPOLayer: y = X @ W^T + bias, W = dense collapse of 3-core MPO.
//   1) build_w_fused (R15-proven): per block (ii, 64 jj): T01 slice in smem,
//      W tile = T01 x core2 -> fp16(W * 2^14). No global T01.
//   2) Xhf = fp16(x)
//   3) Y = (Xhf @ Whf^T) * 2^-14 + bias   single-term fp16 HMMA GEMM,
//      3-stage cp.async (R11 schedule) + register-level fragment
//      double-buffering (ldsm of step i+1 issued before MMAs of step i).
// ===========================================================================

#define KDIM 4096
#define MDIM 1024
#define NDIM 4096
#define WSCALE 16384.0f
#define WINV   (1.0f / 16384.0f)

__device__ __half  g_Whf[(size_t)4096 * 4096]; // 32 MB (W * 2^14)
__device__ __half  g_Xhf[(size_t)1024 * 4096]; // 8 MB

// ---------------------------------------------------------------------------
// helpers
// ---------------------------------------------------------------------------
__device__ __forceinline__ uint32_t smem_u32(const void* p) {
    uint32_t a;
    asm("{ .reg .u64 t; cvta.to.shared.u64 t, %1; cvt.u32.u64 %0, t; }"
        : "=r"(a) : "l"(p));
    return a;
}

__device__ __forceinline__ void cpasync16(uint32_t dst, const void* src) {
    asm volatile("cp.async.cg.shared.global [%0], [%1], 16;"
                 :: "r"(dst), "l"(src) : "memory");
}

__device__ __forceinline__ void ldsm4(uint32_t& r0, uint32_t& r1,
                                      uint32_t& r2, uint32_t& r3, uint32_t a) {
    asm volatile("ldmatrix.sync.aligned.m8n8.x4.shared.b16 {%0,%1,%2,%3}, [%4];"
                 : "=r"(r0), "=r"(r1), "=r"(r2), "=r"(r3) : "r"(a));
}

__device__ __forceinline__ void mma16816(float* d, const uint32_t* a,
                                         uint32_t b0, uint32_t b1) {
    asm volatile(
        "mma.sync.aligned.m16n8k16.row.col.f32.f16.f16.f32 "
        "{%0,%1,%2,%3}, {%4,%5,%6,%7}, {%8,%9}, {%0,%1,%2,%3};"
        : "+f"(d[0]), "+f"(d[1]), "+f"(d[2]), "+f"(d[3])
        : "r"(a[0]), "r"(a[1]), "r"(a[2]), "r"(a[3]), "r"(b0), "r"(b1));
}

// ---------------------------------------------------------------------------
// Kernel 1 (FUSED W BUILD, R15): block = (ii, jjb of 64).
//   t01t[r2][jjloc] = sum_r1 c0[i1,j1,r1] * c1[r1,i2,j2,r2]   (in smem)
//   W[ii*16+i3, jjb*16.. ] = sum_r2 t01t * c2 -> fp16 * 2^14
// Phase-1 lane order: r2q fastest -> c1 loads coalesced.
// ---------------------------------------------------------------------------
#define T01T_PITCH 68
#define NWBLK 1024

__global__ __launch_bounds__(256)
void build_w_fused_kernel(const float* __restrict__ c0,
                          const float* __restrict__ c1,
                          const float* __restrict__ c2) {
    __shared__ __align__(16) float c2s[32 * 256];
    __shared__ __align__(16) float t01t[32 * T01T_PITCH];

    const int tid = threadIdx.x;
    const int ii  = blockIdx.x >> 2;          // 0..255
    const int jjb = (blockIdx.x & 3) * 64;    // 0,64,128,192
    const int i1  = ii >> 4, i2 = ii & 15;

#pragma unroll
    for (int c = tid; c < 2048; c += 256)
        *(float4*)&c2s[c * 4] = *(const float4*)&c2[c * 4];

    {
        const int r2q = tid & 7;
        const int j2  = (tid >> 3) & 15;
        const int j1p = tid >> 7;              // 0..1
        const float4* b = (const float4*)(c1 + i2 * 512 + j2 * 32 + r2q * 4);
        const float*  a = c0 + ((i1 * 16 + (jjb >> 4) + j1p * 2)) * 32;

        float4 s[2];
        s[0] = make_float4(0.f, 0.f, 0.f, 0.f);
        s[1] = make_float4(0.f, 0.f, 0.f, 0.f);
#pragma unroll
        for (int r1 = 0; r1 < 32; ++r1) {
            float4 bv = b[(size_t)r1 * 2048];
#pragma unroll
            for (int v = 0; v < 2; ++v) {
                float av = a[v * 32 + r1];
                s[v].x += av * bv.x; s[v].y += av * bv.y;
                s[v].z += av * bv.z; s[v].w += av * bv.w;
            }
        }
#pragma unroll
        for (int v = 0; v < 2; ++v) {
            int jjloc = (j1p * 2 + v) * 16 + j2;
            t01t[(r2q * 4 + 0) * T01T_PITCH + jjloc] = s[v].x;
            t01t[(r2q * 4 + 1) * T01T_PITCH + jjloc] = s[v].y;
            t01t[(r2q * 4 + 2) * T01T_PITCH + jjloc] = s[v].z;
            t01t[(r2q * 4 + 3) * T01T_PITCH + jjloc] = s[v].w;
        }
    }
    __syncthreads();

    const int i3  = tid >> 4;
    const int jjg = tid & 15;

    float acc[4][16];
#pragma unroll
    for (int a = 0; a < 4; ++a)
#pragma unroll
        for (int b = 0; b < 16; ++b) acc[a][b] = 0.f;

#pragma unroll
    for (int r2 = 0; r2 < 32; ++r2) {
        float4 tv = *(const float4*)&t01t[r2 * T01T_PITCH + jjg * 4];
        const float* crow = &c2s[r2 * 256 + i3 * 16];
        float4 cv0 = *(const float4*)&crow[0];
        float4 cv1 = *(const float4*)&crow[4];
        float4 cv2 = *(const float4*)&crow[8];
        float4 cv3 = *(const float4*)&crow[12];
        float cva[16] = {cv0.x, cv0.y, cv0.z, cv0.w, cv1.x, cv1.y, cv1.z, cv1.w,
                         cv2.x, cv2.y, cv2.z, cv2.w, cv3.x, cv3.y, cv3.z, cv3.w};
        float tva[4] = {tv.x, tv.y, tv.z, tv.w};
#pragma unroll
        for (int a = 0; a < 4; ++a)
#pragma unroll
            for (int b = 0; b < 16; ++b)
                acc[a][b] += tva[a] * cva[b];
    }

    const size_t rowoff = (size_t)(ii * 16 + i3) * 4096;
#pragma unroll
    for (int a = 0; a < 4; ++a) {
        const size_t o = rowoff + (size_t)(jjb + jjg * 4 + a) * 16;
        __half2 buf[8];
#pragma unroll
        for (int p = 0; p < 8; ++p)
            buf[p] = __half2(__float2half(acc[a][2 * p] * WSCALE),
                             __float2half(acc[a][2 * p + 1] * WSCALE));
        *(uint4*)(g_Whf + o)     = *(uint4*)&buf[0];
        *(uint4*)(g_Whf + o + 8) = *(uint4*)&buf[4];
    }
}

// ---------------------------------------------------------------------------
// Kernel 2: X -> fp16
// ---------------------------------------------------------------------------
__global__ void split_x_kernel(const float* __restrict__ x) {
    int idx = blockIdx.x * blockDim.x + threadIdx.x;   // over 1M float4s
    float4 v = ((const float4*)x)[idx];
    __half2* Hp = (__half2*)g_Xhf;
    Hp[idx * 2 + 0] = __half2(__float2half(v.x), __float2half(v.y));
    Hp[idx * 2 + 1] = __half2(__float2half(v.z), __float2half(v.w));
}

// ---------------------------------------------------------------------------
// Kernel 3: fp16 HMMA GEMM. C = (Xhf @ Whf^T) * 2^-14 + bias
// CTA 128x128, BK=64, SW128 swizzle, 3-stage cp.async, 256 threads,
// 8 warps = 4(M) x 2(N), warp tile 32x64, 2 CTAs/SM.
// NEW: flat 16-step (ks,c) loop with register frag double-buffering.
// ---------------------------------------------------------------------------
#define GBM 128
#define GBN 128
#define GBK 64
#define NKT (KDIM / GBK)            // 64
#define ST_A 0
#define ST_B 16384
#define STAGE_BYTES 32768
#define NSTAGE 3
#define SMEM_TOTAL (NSTAGE * STAGE_BYTES)   // 96 KB -> 2 CTAs/SM
#define NTHREADS 256

__device__ __forceinline__ void load_stage(uint32_t st, int bm, int bn,
                                           int kt, int tid) {
    const size_t krow = (size_t)kt * 128;     // byte offset within K row
#pragma unroll
    for (int c = tid; c < 2048; c += NTHREADS) {   // A:1024 + B:1024 chunks
        int arr = c >> 10;                  // 0 = A, 1 = B
        int r   = c & 1023;
        int row = r >> 3, ch = r & 7;
        uint32_t so = (uint32_t)(row * 128 + ch * 16);
        so ^= (so >> 3) & 0x70;
        if (arr == 0) {
            const size_t ga = (size_t)(bm + row) * 8192 + krow + ch * 16;
            cpasync16(st + ST_A + so, (const char*)g_Xhf + ga);
        } else {
            const size_t gb = (size_t)(bn + row) * 8192 + krow + ch * 16;
            cpasync16(st + ST_B + so, (const char*)g_Whf + gb);
        }
    }
}

__global__ __launch_bounds__(NTHREADS, 2)
void gemm_mma_kernel(const float* __restrict__ bias, float* __restrict__ C) {
    extern __shared__ __align__(1024) char smem[];
    const uint32_t sbase = smem_u32(smem);
    const int tid  = threadIdx.x;
    const int lane = tid & 31;
    const int wid  = tid >> 5;
    const int wm = wid & 3;          // 4 M-warps (32 rows each)
    const int wn = wid >> 2;         // 2 N-warps (64 cols each)
    const int bm = blockIdx.y * GBM;
    const int bn = blockIdx.x * GBN;

    const int lrow = lane & 15;
    const uint32_t lchunk = (uint32_t)((lane >> 4) * 16);

    uint32_t a_base[2], a_mask[2];
#pragma unroll
    for (int mt = 0; mt < 2; ++mt) {
        int r = wm * 32 + mt * 16 + lrow;
        a_base[mt] = (uint32_t)(r * 128);
        a_mask[mt] = (uint32_t)((r & 7) << 4);
    }
    uint32_t b_base[4], b_mask[4];
#pragma unroll
    for (int c = 0; c < 4; ++c) {
        int r = wn * 64 + c * 16 + lrow;
        b_base[c] = (uint32_t)(r * 128);
        b_mask[c] = (uint32_t)((r & 7) << 4);
    }

    float acc[2][8][4];
#pragma unroll
    for (int mt = 0; mt < 2; ++mt)
#pragma unroll
        for (int nt = 0; nt < 8; ++nt)
#pragma unroll
            for (int e = 0; e < 4; ++e) acc[mt][nt][e] = 0.f;

    load_stage(sbase + 0 * STAGE_BYTES, bm, bn, 0, tid);
    asm volatile("cp.async.commit_group;" ::: "memory");
    load_stage(sbase + 1 * STAGE_BYTES, bm, bn, 1, tid);
    asm volatile("cp.async.commit_group;" ::: "memory");

    int slot = 0;
    for (int kt = 0; kt < NKT; ++kt) {
        if (kt + 1 < NKT)
            asm volatile("cp.async.wait_group 1;" ::: "memory");
        else
            asm volatile("cp.async.wait_group 0;" ::: "memory");
        __syncthreads();   // all warps done with slot (kt-1)%3; tile kt landed

        if (kt + 2 < NKT) {
            int ns = slot + 2; if (ns >= NSTAGE) ns -= NSTAGE;
            load_stage(sbase + ns * STAGE_BYTES, bm, bn, kt + 2, tid);
            asm volatile("cp.async.commit_group;" ::: "memory");
        }

        const uint32_t st = sbase + slot * STAGE_BYTES;

        // -------- flat 16-step (ks,c) loop, frag double-buffered --------
        uint32_t ahb[2][2][4];   // [buf][mt][4]
        uint32_t bhb[2][4];      // [buf][4]
        // initial loads: A for ks=0, B for (ks=0, c=0)
#pragma unroll
        for (int mt = 0; mt < 2; ++mt) {
            uint32_t col = lchunk ^ a_mask[mt];
            ldsm4(ahb[0][mt][0], ahb[0][mt][1], ahb[0][mt][2], ahb[0][mt][3],
                  st + ST_A + a_base[mt] + col);
        }
        {
            uint32_t col = lchunk ^ b_mask[0];
            ldsm4(bhb[0][0], bhb[0][1], bhb[0][2], bhb[0][3],
                  st + ST_B + b_base[0] + col);
        }
#pragma unroll
        for (int step = 0; step < 16; ++step) {
            const int ks = step >> 2, c = step & 3;
            const int ab = ks & 1, bb = step & 1;
            if (step < 15) {
                const int ns = step + 1;
                const int nks = ns >> 2, nc = ns & 3;
                const uint32_t nkb = (uint32_t)(nks * 32);
                uint32_t colb = (lchunk + nkb) ^ b_mask[nc];
                ldsm4(bhb[bb ^ 1][0], bhb[bb ^ 1][1],
                      bhb[bb ^ 1][2], bhb[bb ^ 1][3],
                      st + ST_B + b_base[nc] + colb);
                if (nc == 0) {
#pragma unroll
                    for (int mt = 0; mt < 2; ++mt) {
                        uint32_t cola = (lchunk + nkb) ^ a_mask[mt];
                        ldsm4(ahb[nks & 1][mt][0], ahb[nks & 1][mt][1],
                              ahb[nks & 1][mt][2], ahb[nks & 1][mt][3],
                              st + ST_A + a_base[mt] + cola);
                    }
                }
            }
#pragma unroll
            for (int mt = 0; mt < 2; ++mt)
#pragma unroll
                for (int o = 0; o < 2; ++o)
                    mma16816(acc[mt][c * 2 + o], ahb[ab][mt],
                             bhb[bb][o], bhb[bb][o + 2]);
        }
        ++slot; if (slot >= NSTAGE) slot = 0;
    }

    // epilogue: undo 2^14 W scaling (exact), add bias
    const int gq = lane >> 2, rq = lane & 3;
#pragma unroll
    for (int mt = 0; mt < 2; ++mt) {
        const int r0 = bm + wm * 32 + mt * 16 + gq;
#pragma unroll
        for (int nt = 0; nt < 8; ++nt) {
            const int col = bn + wn * 64 + nt * 8 + rq * 2;
            float2 bv = *(const float2*)&bias[col];
            float2 o0 = make_float2(acc[mt][nt][0] * WINV + bv.x,
                                    acc[mt][nt][1] * WINV + bv.y);
            float2 o1 = make_float2(acc[mt][nt][2] * WINV + bv.x,
                                    acc[mt][nt][3] * WINV + bv.y);
            *(float2*)&C[(size_t)r0 * NDIM + col]       = o0;
            *(float2*)&C[(size_t)(r0 + 8) * NDIM + col] = o1;
        }
    }
}

// ---------------------------------------------------------------------------
extern "C" void kernel_launch(void* const* d_in, const int* in_sizes, int n_in,
                              void* d_out, int out_size) {
    const float* x     = (const float*)d_in[0];
    const float* core0 = (const float*)d_in[1];
    const float* core1 = (const float*)d_in[2];
    const float* core2 = (const float*)d_in[3];
    const float* bias  = (const float*)d_in[4];
    float* out = (float*)d_out;

    build_w_fused_kernel<<<NWBLK, 256>>>(core0, core1, core2);
    split_x_kernel<<<(MDIM * KDIM / 4) / 256, 256>>>(x);

    cudaFuncSetAttribute(gemm_mma_kernel,
                         cudaFuncAttributeMaxDynamicSharedMemorySize, SMEM_TOTAL);
    gemm_mma_kernel<<<dim3(NDIM / GBN, MDIM / GBM), NTHREADS, SMEM_TOTAL>>>(bias, out);
}